// round 5
// baseline (speedup 1.0000x reference)
#include <cuda_runtime.h>
#include <cuda_fp16.h>
#include <cstdint>

// Problem constants
#define NTRI 32
#define TSTEPS 512
#define IDIM 64
#define NN 4096
#define RR 8
#define ODIM 64
#define DT 0.1f

#define XSEQ_ELEMS (32ll * 513 * 4096)

#define CLUSTER_SZ 4
#define NPC (NN / CLUSTER_SZ)      // 1024 neurons per CTA
#define SCAN_THREADS 256
#define NPT (NPC / SCAN_THREADS)   // 4 neurons per thread

// Scratch: inp_proj [b][t][j] : 32*512*4096 floats = 268 MB
__device__ float g_uproj[(size_t)NTRI * TSTEPS * NN];

__device__ __forceinline__ float sigmoid_fast(float x) {
    float t;
    asm("tanh.approx.f32 %0, %1;" : "=f"(t) : "f"(0.5f * x));
    return fmaf(0.5f, t, 0.5f);
}

__device__ __forceinline__ void red_shared_f32(float* p, float v) {
    unsigned addr = (unsigned)__cvta_generic_to_shared(p);
    asm volatile("red.shared.add.f32 [%0], %1;" :: "r"(addr), "f"(v) : "memory");
}

// remote (cluster) shared-memory atomic add: mapa local addr to target rank
__device__ __forceinline__ void red_cluster_f32(float* p, unsigned target, float v) {
    unsigned addr = (unsigned)__cvta_generic_to_shared(p);
    asm volatile(
        "{\n\t"
        ".reg .b32 ra;\n\t"
        "mapa.shared::cluster.u32 ra, %0, %1;\n\t"
        "red.relaxed.cluster.shared::cluster.add.f32 [ra], %2;\n\t"
        "}"
        :: "r"(addr), "r"(target), "f"(v) : "memory");
}

__device__ __forceinline__ void cluster_sync_() {
    asm volatile("barrier.cluster.arrive.aligned;" ::: "memory");
    asm volatile("barrier.cluster.wait.aligned;" ::: "memory");
}

__device__ __forceinline__ __half2 shfl_xor_h2(__half2 v, int m) {
    unsigned u = *reinterpret_cast<unsigned*>(&v);
    u = __shfl_xor_sync(0xffffffffu, u, m);
    return *reinterpret_cast<__half2*>(&u);
}

// ---------------------------------------------------------------------------
// Kernel 1: inp_proj[b][t][j] = sum_i inp[b][t][i] * B[j][i]
// ---------------------------------------------------------------------------
__global__ void __launch_bounds__(256) proj_kernel(const float* __restrict__ inp,
                                                   const float* __restrict__ B) {
    __shared__ float a_s[32][132];  // [k][bt]
    __shared__ float b_s[32][68];   // [k][j]

    const int tid = threadIdx.x;
    const int g0 = blockIdx.y * 128;   // bt base
    const int jb0 = blockIdx.x * 64;   // j base
    const int ty = tid >> 4;
    const int tx = tid & 15;
    const int bt0 = ty * 8;
    const int j0 = tx * 4;

    float acc[8][4];
#pragma unroll
    for (int i = 0; i < 8; i++)
#pragma unroll
        for (int j = 0; j < 4; j++) acc[i][j] = 0.f;

#pragma unroll
    for (int kc = 0; kc < 2; kc++) {
        if (kc) __syncthreads();
#pragma unroll
        for (int it = 0; it < 4; it++) {
            int q = tid + it * 256;
            int r = q >> 3;
            int c4 = q & 7;
            float4 av = *(const float4*)(inp + (size_t)(g0 + r) * 64 + kc * 32 + c4 * 4);
            a_s[c4 * 4 + 0][r] = av.x;
            a_s[c4 * 4 + 1][r] = av.y;
            a_s[c4 * 4 + 2][r] = av.z;
            a_s[c4 * 4 + 3][r] = av.w;
        }
#pragma unroll
        for (int it = 0; it < 2; it++) {
            int q = tid + it * 256;
            int jr = q >> 3;
            int c4 = q & 7;
            float4 bv = *(const float4*)(B + (size_t)(jb0 + jr) * 64 + kc * 32 + c4 * 4);
            b_s[c4 * 4 + 0][jr] = bv.x;
            b_s[c4 * 4 + 1][jr] = bv.y;
            b_s[c4 * 4 + 2][jr] = bv.z;
            b_s[c4 * 4 + 3][jr] = bv.w;
        }
        __syncthreads();
#pragma unroll
        for (int k = 0; k < 32; k++) {
            float4 a0 = *(const float4*)&a_s[k][bt0];
            float4 a1 = *(const float4*)&a_s[k][bt0 + 4];
            float4 bb = *(const float4*)&b_s[k][j0];
            float af[8] = {a0.x, a0.y, a0.z, a0.w, a1.x, a1.y, a1.z, a1.w};
            float bf[4] = {bb.x, bb.y, bb.z, bb.w};
#pragma unroll
            for (int i = 0; i < 8; i++)
#pragma unroll
                for (int j = 0; j < 4; j++) acc[i][j] = fmaf(af[i], bf[j], acc[i][j]);
        }
    }
#pragma unroll
    for (int i = 0; i < 8; i++) {
        float4 o = make_float4(acc[i][0], acc[i][1], acc[i][2], acc[i][3]);
        *(float4*)(g_uproj + (size_t)(g0 + bt0 + i) * NN + jb0 + j0) = o;
    }
}

// ---------------------------------------------------------------------------
// Kernel 2: recurrence. 4-CTA cluster per trial (grid=128, 128 SMs busy).
// Each CTA: 1024 neurons, 256 threads, 4 neurons/thread. Rank-8 bottleneck:
// intra-CTA (warp fold + red.shared) -> cross-CTA DSMEM red + cluster.sync.
// ---------------------------------------------------------------------------
__global__ void __cluster_dims__(CLUSTER_SZ, 1, 1)
__launch_bounds__(SCAN_THREADS, 1) rnn_scan_kernel(const float* __restrict__ mg,
                                                   const float* __restrict__ ng,
                                                   float* __restrict__ xseq) {
    const int b = blockIdx.x >> 2;          // trial
    const unsigned rank = blockIdx.x & 3;   // rank within cluster
    const int tid = threadIdx.x;
    const unsigned lane = tid & 31;
    const unsigned warp = tid >> 5;
    const int j0 = (int)rank * NPC + tid * NPT;  // global neuron base

    __shared__ float vtot[4][8];        // rotating, accumulated via cluster reds
    __shared__ float local_part[2][8];  // rotating, intra-CTA partials

    // load n, m rows as packed fp16 pairs; m pre-scaled by DT
    __half2 nP[NPT][4], mP[NPT][4];
#pragma unroll
    for (int k = 0; k < NPT; k++) {
        const float* nr = ng + (size_t)(j0 + k) * RR;
        const float* mr = mg + (size_t)(j0 + k) * RR;
#pragma unroll
        for (int p = 0; p < 4; p++) {
            nP[k][p] = __floats2half2_rn(nr[2 * p], nr[2 * p + 1]);
            mP[k][p] = __floats2half2_rn(mr[2 * p] * DT, mr[2 * p + 1] * DT);
        }
    }

    float x[NPT];
    __half2 sd[NPT];
    const __half2 half05 = __floats2half2_rn(0.5f, 0.5f);
#pragma unroll
    for (int k = 0; k < NPT; k++) {
        x[k] = 0.f;
        sd[k] = half05;
    }

    if (tid < 32) ((float*)vtot)[tid] = 0.f;
    if (tid < 16) ((float*)local_part)[tid] = 0.f;

    float* xrow0 = xseq + (size_t)b * 513 * NN;
    const float4 z4 = make_float4(0.f, 0.f, 0.f, 0.f);
    *(float4*)(xrow0 + j0) = z4;  // x_seq[b][0][slice] = 0

    const float* up = g_uproj + (size_t)b * TSTEPS * NN + j0;
    const float keep = 1.0f - DT;
    const float invN = 1.0f / (float)NN;
    const bool hi16 = (lane & 16) != 0;
    const bool hi8 = (lane & 8) != 0;

    __syncthreads();
    cluster_sync_();  // all CTAs' vtot/local_part zeroed before any reds

    // prefetch u for step 0
    float4 u0 = __ldg((const float4*)up);

    for (int t = 0; t < TSTEPS; t++) {
        // prefetch u for step t+1
        float4 p0 = (t + 1 < TSTEPS) ? __ldg((const float4*)(up + (size_t)(t + 1) * NN)) : z4;

        // v partials: h[p] = (v[2p], v[2p+1]) contribution of my NPT neurons
        __half2 h[4];
#pragma unroll
        for (int p = 0; p < 4; p++) h[p] = __floats2half2_rn(0.f, 0.f);
#pragma unroll
        for (int k = 0; k < NPT; k++) {
#pragma unroll
            for (int p = 0; p < 4; p++) h[p] = __hfma2(sd[k], nP[k][p], h[p]);
        }

        // folded warp reduce: lanes end as 8-lane groups, leader holds h[0] for q=lane>>3
#pragma unroll
        for (int p = 0; p < 2; p++) {
            __half2 snd = hi16 ? h[p] : h[p + 2];
            __half2 rcv = shfl_xor_h2(snd, 16);
            h[p] = __hadd2(hi16 ? h[p + 2] : h[p], rcv);
        }
        {
            __half2 snd = hi8 ? h[0] : h[1];
            __half2 rcv = shfl_xor_h2(snd, 8);
            h[0] = __hadd2(hi8 ? h[1] : h[0], rcv);
        }
        h[0] = __hadd2(h[0], shfl_xor_h2(h[0], 4));
        h[0] = __hadd2(h[0], shfl_xor_h2(h[0], 2));
        h[0] = __hadd2(h[0], shfl_xor_h2(h[0], 1));

        const int cur = t & 3;    // vtot buffer
        const int cur2 = t & 1;   // local_part buffer
        if ((lane & 7) == 0) {
            const int q = lane >> 3;
            float2 vf = __half22float2(h[0]);
            red_shared_f32(&local_part[cur2][2 * q], vf.x);
            red_shared_f32(&local_part[cur2][2 * q + 1], vf.y);
        }
        __syncthreads();  // drain local reds; also fences prior-step vtot reads

        // warp 0: broadcast 8 local partials to all 4 CTAs' vtot[cur]
        if (warp == 0) {
            const unsigned target = lane >> 3;
            const int r = lane & 7;
            float val = local_part[cur2][r];
            red_cluster_f32(&vtot[cur][r], target, val);
        }
        // zero buffers for reuse (safe per rotation analysis)
        if (tid < 8) {
            local_part[cur2 ^ 1][tid] = 0.f;  // last read by warp0 at step t-1
            vtot[(t + 2) & 3][tid] = 0.f;     // t+2 reds gated behind our t+1 arrive
        }

        cluster_sync_();  // release our reds / acquire everyone's

        float4 va = *(const float4*)&vtot[cur][0];
        float4 vb = *(const float4*)&vtot[cur][4];
        __half2 vh[4];
        vh[0] = __floats2half2_rn(va.x * invN, va.y * invN);
        vh[1] = __floats2half2_rn(va.z * invN, va.w * invN);
        vh[2] = __floats2half2_rn(vb.x * invN, vb.y * invN);
        vh[3] = __floats2half2_rn(vb.z * invN, vb.w * invN);

        float ua[4] = {u0.x, u0.y, u0.z, u0.w};

#pragma unroll
        for (int k = 0; k < NPT; k++) {
            __half2 rh = __hmul2(vh[0], mP[k][0]);
            rh = __hfma2(vh[1], mP[k][1], rh);
            rh = __hfma2(vh[2], mP[k][2], rh);
            rh = __hfma2(vh[3], mP[k][3], rh);
            float rec = __low2float(rh) + __high2float(rh);  // already scaled by DT
            x[k] = fmaf(keep, x[k], fmaf(DT, ua[k], rec));
            float s = sigmoid_fast(x[k]);
            sd[k] = __half2half2(__float2half_rn(s));
        }

        float* dst = xrow0 + (size_t)(t + 1) * NN + j0;
        *(float4*)dst = make_float4(x[0], x[1], x[2], x[3]);

        u0 = p0;
    }
}

// ---------------------------------------------------------------------------
// Kernel 3: y[b][t][o] = sum_j sigmoid(x_seq[b][t+1][j]) * W[o][j]
// ---------------------------------------------------------------------------
__global__ void __launch_bounds__(256) out_kernel(const float* __restrict__ xseq,
                                                  const float* __restrict__ W,
                                                  float* __restrict__ out2) {
    __shared__ float x_s[32][68];
    __shared__ float w_s[32][68];

    const int tid = threadIdx.x;
    const int g0 = blockIdx.x * 64;
    const int bb = g0 >> 9;
    const int t0 = g0 & 511;
    const float* xbase = xseq + (size_t)bb * 513 * NN + (size_t)(t0 + 1) * NN;

    const int ty = tid >> 4;
    const int tx = tid & 15;
    const int bt0 = ty * 4;
    const int o0 = tx * 4;

    float acc[4][4];
#pragma unroll
    for (int i = 0; i < 4; i++)
#pragma unroll
        for (int j = 0; j < 4; j++) acc[i][j] = 0.f;

    for (int kc = 0; kc < NN / 32; kc++) {
        if (kc) __syncthreads();
#pragma unroll
        for (int it = 0; it < 2; it++) {
            int q = tid + it * 256;
            int r = q >> 3;
            int c4 = q & 7;
            float4 xv = *(const float4*)(xbase + (size_t)r * NN + kc * 32 + c4 * 4);
            x_s[c4 * 4 + 0][r] = sigmoid_fast(xv.x);
            x_s[c4 * 4 + 1][r] = sigmoid_fast(xv.y);
            x_s[c4 * 4 + 2][r] = sigmoid_fast(xv.z);
            x_s[c4 * 4 + 3][r] = sigmoid_fast(xv.w);
        }
#pragma unroll
        for (int it = 0; it < 2; it++) {
            int q = tid + it * 256;
            int o = q >> 3;
            int c4 = q & 7;
            float4 wv = *(const float4*)(W + (size_t)o * NN + kc * 32 + c4 * 4);
            w_s[c4 * 4 + 0][o] = wv.x;
            w_s[c4 * 4 + 1][o] = wv.y;
            w_s[c4 * 4 + 2][o] = wv.z;
            w_s[c4 * 4 + 3][o] = wv.w;
        }
        __syncthreads();
#pragma unroll
        for (int k = 0; k < 32; k++) {
            float4 a = *(const float4*)&x_s[k][bt0];
            float4 w4 = *(const float4*)&w_s[k][o0];
            float af[4] = {a.x, a.y, a.z, a.w};
            float wf[4] = {w4.x, w4.y, w4.z, w4.w};
#pragma unroll
            for (int i = 0; i < 4; i++)
#pragma unroll
                for (int j = 0; j < 4; j++) acc[i][j] = fmaf(af[i], wf[j], acc[i][j]);
        }
    }
#pragma unroll
    for (int i = 0; i < 4; i++) {
        float4 o = make_float4(acc[i][0], acc[i][1], acc[i][2], acc[i][3]);
        *(float4*)(out2 + (size_t)(g0 + bt0 + i) * ODIM + o0) = o;
    }
}

// ---------------------------------------------------------------------------
extern "C" void kernel_launch(void* const* d_in, const int* in_sizes, int n_in,
                              void* d_out, int out_size) {
    const float* inp = (const float*)d_in[0];  // [32,512,64]
    const float* B = (const float*)d_in[1];    // [4096,64]
    const float* W = (const float*)d_in[2];    // [64,4096]
    const float* m = (const float*)d_in[3];    // [4096,8]
    const float* n = (const float*)d_in[4];    // [4096,8]

    float* xseq = (float*)d_out;               // [32,513,4096]
    float* out2 = (float*)d_out + XSEQ_ELEMS;  // [32,512,64]

    {
        dim3 grid(NN / 64, (NTRI * TSTEPS) / 128);
        proj_kernel<<<grid, 256>>>(inp, B);
    }
    rnn_scan_kernel<<<NTRI * CLUSTER_SZ, SCAN_THREADS>>>(m, n, xseq);
    out_kernel<<<(NTRI * TSTEPS) / 64, 256>>>(xseq, W, out2);
}

// round 6
// speedup vs baseline: 1.2907x; 1.2907x over previous
#include <cuda_runtime.h>
#include <cuda_fp16.h>
#include <cstdint>

// Problem constants
#define NTRI 32
#define TSTEPS 512
#define IDIM 64
#define NN 4096
#define RR 8
#define ODIM 64
#define DT 0.1f

#define XSEQ_ELEMS (32ll * 513 * 4096)

// Scratch: inp_proj [b][t][j] : 32*512*4096 floats = 268 MB
__device__ float g_uproj[(size_t)NTRI * TSTEPS * NN];

__device__ __forceinline__ float sigmoid_fast(float x) {
    float t;
    asm("tanh.approx.f32 %0, %1;" : "=f"(t) : "f"(0.5f * x));
    return fmaf(0.5f, t, 0.5f);
}

__device__ __forceinline__ __half2 shfl_xor_h2(__half2 v, int m) {
    unsigned u = *reinterpret_cast<unsigned*>(&v);
    u = __shfl_xor_sync(0xffffffffu, u, m);
    return *reinterpret_cast<__half2*>(&u);
}

// ---------------------------------------------------------------------------
// Kernel 1: inp_proj[b][t][j] = sum_i inp[b][t][i] * B[j][i]
// ---------------------------------------------------------------------------
__global__ void __launch_bounds__(256) proj_kernel(const float* __restrict__ inp,
                                                   const float* __restrict__ B) {
    __shared__ float a_s[32][132];  // [k][bt]
    __shared__ float b_s[32][68];   // [k][j]

    const int tid = threadIdx.x;
    const int g0 = blockIdx.y * 128;   // bt base
    const int jb0 = blockIdx.x * 64;   // j base
    const int ty = tid >> 4;
    const int tx = tid & 15;
    const int bt0 = ty * 8;
    const int j0 = tx * 4;

    float acc[8][4];
#pragma unroll
    for (int i = 0; i < 8; i++)
#pragma unroll
        for (int j = 0; j < 4; j++) acc[i][j] = 0.f;

#pragma unroll
    for (int kc = 0; kc < 2; kc++) {
        if (kc) __syncthreads();
#pragma unroll
        for (int it = 0; it < 4; it++) {
            int q = tid + it * 256;
            int r = q >> 3;
            int c4 = q & 7;
            float4 av = *(const float4*)(inp + (size_t)(g0 + r) * 64 + kc * 32 + c4 * 4);
            a_s[c4 * 4 + 0][r] = av.x;
            a_s[c4 * 4 + 1][r] = av.y;
            a_s[c4 * 4 + 2][r] = av.z;
            a_s[c4 * 4 + 3][r] = av.w;
        }
#pragma unroll
        for (int it = 0; it < 2; it++) {
            int q = tid + it * 256;
            int jr = q >> 3;
            int c4 = q & 7;
            float4 bv = *(const float4*)(B + (size_t)(jb0 + jr) * 64 + kc * 32 + c4 * 4);
            b_s[c4 * 4 + 0][jr] = bv.x;
            b_s[c4 * 4 + 1][jr] = bv.y;
            b_s[c4 * 4 + 2][jr] = bv.z;
            b_s[c4 * 4 + 3][jr] = bv.w;
        }
        __syncthreads();
#pragma unroll
        for (int k = 0; k < 32; k++) {
            float4 a0 = *(const float4*)&a_s[k][bt0];
            float4 a1 = *(const float4*)&a_s[k][bt0 + 4];
            float4 bb = *(const float4*)&b_s[k][j0];
            float af[8] = {a0.x, a0.y, a0.z, a0.w, a1.x, a1.y, a1.z, a1.w};
            float bf[4] = {bb.x, bb.y, bb.z, bb.w};
#pragma unroll
            for (int i = 0; i < 8; i++)
#pragma unroll
                for (int j = 0; j < 4; j++) acc[i][j] = fmaf(af[i], bf[j], acc[i][j]);
        }
    }
#pragma unroll
    for (int i = 0; i < 8; i++) {
        float4 o = make_float4(acc[i][0], acc[i][1], acc[i][2], acc[i][3]);
        *(float4*)(g_uproj + (size_t)(g0 + bt0 + i) * NN + jb0 + j0) = o;
    }
}

// ---------------------------------------------------------------------------
// Kernel 2: recurrence. One CTA per trial, 512 threads, 8 neurons/thread.
// Atomic-free rank-8 reduction: warp fold -> STS 64 half2 partials (double
// buffered) -> one barrier -> every-warp butterfly LDS reduce. u prefetched
// one full step ahead.
// ---------------------------------------------------------------------------
__global__ void __launch_bounds__(512, 1) rnn_scan_kernel(const float* __restrict__ mg,
                                                          const float* __restrict__ ng,
                                                          float* __restrict__ xseq) {
    const int b = blockIdx.x;
    const int tid = threadIdx.x;
    const int j0 = tid * 8;
    const unsigned lane = tid & 31;
    const unsigned warp = tid >> 5;

    // partials: [buf][q][warp], q = r-pair index; 64 half2 per buffer
    __shared__ __half2 part[2][4][16];

    // load n, m rows as packed fp16 pairs; m pre-scaled by DT
    __half2 nP[8][4], mP[8][4];
#pragma unroll
    for (int k = 0; k < 8; k++) {
        const float* nr = ng + (size_t)(j0 + k) * RR;
        const float* mr = mg + (size_t)(j0 + k) * RR;
#pragma unroll
        for (int p = 0; p < 4; p++) {
            nP[k][p] = __floats2half2_rn(nr[2 * p], nr[2 * p + 1]);
            mP[k][p] = __floats2half2_rn(mr[2 * p] * DT, mr[2 * p + 1] * DT);
        }
    }

    float x[8];
    __half2 sd[8];
    const __half2 half05 = __floats2half2_rn(0.5f, 0.5f);
#pragma unroll
    for (int k = 0; k < 8; k++) {
        x[k] = 0.f;
        sd[k] = half05;
    }

    float* xrow0 = xseq + (size_t)b * 513 * NN;
    const float4 z4 = make_float4(0.f, 0.f, 0.f, 0.f);
    *(float4*)(xrow0 + j0) = z4;
    *(float4*)(xrow0 + j0 + 4) = z4;

    const float* up = g_uproj + (size_t)b * TSTEPS * NN + j0;
    const float keep = 1.0f - DT;
    const __half2 invN2 = __floats2half2_rn(1.0f / (float)NN, 1.0f / (float)NN);
    const bool hi16 = (lane & 16) != 0;
    const bool hi8 = (lane & 8) != 0;
    const bool lo16 = !hi16;

    // prefetch u for step 0
    float4 u0 = __ldg((const float4*)up);
    float4 u1 = __ldg((const float4*)(up + 4));

    for (int t = 0; t < TSTEPS; t++) {
        // prefetch u for step t+1 (consumed one full step later)
        float4 p0, p1;
        if (t + 1 < TSTEPS) {
            p0 = __ldg((const float4*)(up + (size_t)(t + 1) * NN));
            p1 = __ldg((const float4*)(up + (size_t)(t + 1) * NN + 4));
        } else {
            p0 = z4; p1 = z4;
        }

        // v partials in half2: h[p] = (v[2p], v[2p+1]) over my 8 neurons
        __half2 h[4];
#pragma unroll
        for (int p = 0; p < 4; p++) h[p] = __floats2half2_rn(0.f, 0.f);
#pragma unroll
        for (int k = 0; k < 8; k++) {
#pragma unroll
            for (int p = 0; p < 4; p++) h[p] = __hfma2(sd[k], nP[k][p], h[p]);
        }

        // folded warp reduce: leader of each 8-lane group holds h[0] for q=lane>>3
#pragma unroll
        for (int p = 0; p < 2; p++) {
            __half2 snd = hi16 ? h[p] : h[p + 2];
            __half2 rcv = shfl_xor_h2(snd, 16);
            h[p] = __hadd2(hi16 ? h[p + 2] : h[p], rcv);
        }
        {
            __half2 snd = hi8 ? h[0] : h[1];
            __half2 rcv = shfl_xor_h2(snd, 8);
            h[0] = __hadd2(hi8 ? h[1] : h[0], rcv);
        }
        h[0] = __hadd2(h[0], shfl_xor_h2(h[0], 4));
        h[0] = __hadd2(h[0], shfl_xor_h2(h[0], 2));
        h[0] = __hadd2(h[0], shfl_xor_h2(h[0], 1));

        const int buf = t & 1;
        if ((lane & 7) == 0) {
            part[buf][lane >> 3][warp] = h[0];  // 64 plain STS, no conflicts to drain
        }
        __syncthreads();

        // butterfly reduce (every warp, redundantly):
        // lane l loads entries l (q0/q1 halves) and l+32 (q2/q3 halves)
        const __half2* flat = &part[buf][0][0];
        __half2 a = flat[lane];
        __half2 c = flat[lane + 32];
#pragma unroll
        for (int d = 8; d > 0; d >>= 1) {
            a = __hadd2(a, shfl_xor_h2(a, d));
            c = __hadd2(c, shfl_xor_h2(c, d));
        }
        // lanes 0-15: a=q0 sum, c=q2 sum; lanes 16-31: a=q1, c=q3
        __half2 a2 = shfl_xor_h2(a, 16);
        __half2 c2 = shfl_xor_h2(c, 16);
        __half2 vh[4];
        vh[0] = __hmul2(lo16 ? a : a2, invN2);
        vh[1] = __hmul2(lo16 ? a2 : a, invN2);
        vh[2] = __hmul2(lo16 ? c : c2, invN2);
        vh[3] = __hmul2(lo16 ? c2 : c, invN2);

        float ua[8] = {u0.x, u0.y, u0.z, u0.w, u1.x, u1.y, u1.z, u1.w};

#pragma unroll
        for (int k = 0; k < 8; k++) {
            __half2 rh = __hmul2(vh[0], mP[k][0]);
            rh = __hfma2(vh[1], mP[k][1], rh);
            rh = __hfma2(vh[2], mP[k][2], rh);
            rh = __hfma2(vh[3], mP[k][3], rh);
            float rec = __low2float(rh) + __high2float(rh);  // scaled by DT already
            x[k] = fmaf(keep, x[k], fmaf(DT, ua[k], rec));
            float s = sigmoid_fast(x[k]);
            sd[k] = __half2half2(__float2half_rn(s));
        }

        float* dst = xrow0 + (size_t)(t + 1) * NN + j0;
        *(float4*)dst = make_float4(x[0], x[1], x[2], x[3]);
        *(float4*)(dst + 4) = make_float4(x[4], x[5], x[6], x[7]);

        u0 = p0; u1 = p1;
    }
}

// ---------------------------------------------------------------------------
// Kernel 3: y[b][t][o] = sum_j sigmoid(x_seq[b][t+1][j]) * W[o][j]
// ---------------------------------------------------------------------------
__global__ void __launch_bounds__(256) out_kernel(const float* __restrict__ xseq,
                                                  const float* __restrict__ W,
                                                  float* __restrict__ out2) {
    __shared__ float x_s[32][68];
    __shared__ float w_s[32][68];

    const int tid = threadIdx.x;
    const int g0 = blockIdx.x * 64;
    const int bb = g0 >> 9;
    const int t0 = g0 & 511;
    const float* xbase = xseq + (size_t)bb * 513 * NN + (size_t)(t0 + 1) * NN;

    const int ty = tid >> 4;
    const int tx = tid & 15;
    const int bt0 = ty * 4;
    const int o0 = tx * 4;

    float acc[4][4];
#pragma unroll
    for (int i = 0; i < 4; i++)
#pragma unroll
        for (int j = 0; j < 4; j++) acc[i][j] = 0.f;

    for (int kc = 0; kc < NN / 32; kc++) {
        if (kc) __syncthreads();
#pragma unroll
        for (int it = 0; it < 2; it++) {
            int q = tid + it * 256;
            int r = q >> 3;
            int c4 = q & 7;
            float4 xv = *(const float4*)(xbase + (size_t)r * NN + kc * 32 + c4 * 4);
            x_s[c4 * 4 + 0][r] = sigmoid_fast(xv.x);
            x_s[c4 * 4 + 1][r] = sigmoid_fast(xv.y);
            x_s[c4 * 4 + 2][r] = sigmoid_fast(xv.z);
            x_s[c4 * 4 + 3][r] = sigmoid_fast(xv.w);
        }
#pragma unroll
        for (int it = 0; it < 2; it++) {
            int q = tid + it * 256;
            int o = q >> 3;
            int c4 = q & 7;
            float4 wv = *(const float4*)(W + (size_t)o * NN + kc * 32 + c4 * 4);
            w_s[c4 * 4 + 0][o] = wv.x;
            w_s[c4 * 4 + 1][o] = wv.y;
            w_s[c4 * 4 + 2][o] = wv.z;
            w_s[c4 * 4 + 3][o] = wv.w;
        }
        __syncthreads();
#pragma unroll
        for (int k = 0; k < 32; k++) {
            float4 a = *(const float4*)&x_s[k][bt0];
            float4 w4 = *(const float4*)&w_s[k][o0];
            float af[4] = {a.x, a.y, a.z, a.w};
            float wf[4] = {w4.x, w4.y, w4.z, w4.w};
#pragma unroll
            for (int i = 0; i < 4; i++)
#pragma unroll
                for (int j = 0; j < 4; j++) acc[i][j] = fmaf(af[i], wf[j], acc[i][j]);
        }
    }
#pragma unroll
    for (int i = 0; i < 4; i++) {
        float4 o = make_float4(acc[i][0], acc[i][1], acc[i][2], acc[i][3]);
        *(float4*)(out2 + (size_t)(g0 + bt0 + i) * ODIM + o0) = o;
    }
}

// ---------------------------------------------------------------------------
extern "C" void kernel_launch(void* const* d_in, const int* in_sizes, int n_in,
                              void* d_out, int out_size) {
    const float* inp = (const float*)d_in[0];  // [32,512,64]
    const float* B = (const float*)d_in[1];    // [4096,64]
    const float* W = (const float*)d_in[2];    // [64,4096]
    const float* m = (const float*)d_in[3];    // [4096,8]
    const float* n = (const float*)d_in[4];    // [4096,8]

    float* xseq = (float*)d_out;               // [32,513,4096]
    float* out2 = (float*)d_out + XSEQ_ELEMS;  // [32,512,64]

    {
        dim3 grid(NN / 64, (NTRI * TSTEPS) / 128);
        proj_kernel<<<grid, 256>>>(inp, B);
    }
    rnn_scan_kernel<<<NTRI, 512>>>(m, n, xseq);
    out_kernel<<<(NTRI * TSTEPS) / 64, 256>>>(xseq, W, out2);
}

// round 7
// speedup vs baseline: 1.3478x; 1.0442x over previous
#include <cuda_runtime.h>
#include <cuda_fp16.h>
#include <cstdint>

// Problem constants
#define NTRI 32
#define TSTEPS 512
#define IDIM 64
#define NN 4096
#define RR 8
#define ODIM 64
#define DT 0.1f

#define XSEQ_ELEMS (32ll * 513 * 4096)

// Scratch: inp_proj [b][t][j] : 32*512*4096 floats = 268 MB
__device__ float g_uproj[(size_t)NTRI * TSTEPS * NN];

__device__ __forceinline__ float sigmoid_fast(float x) {
    float t;
    asm("tanh.approx.f32 %0, %1;" : "=f"(t) : "f"(0.5f * x));
    return fmaf(0.5f, t, 0.5f);
}

__device__ __forceinline__ __half2 shfl_xor_h2(__half2 v, int m) {
    unsigned u = *reinterpret_cast<unsigned*>(&v);
    u = __shfl_xor_sync(0xffffffffu, u, m);
    return *reinterpret_cast<__half2*>(&u);
}

// ---- packed f32x2 (Blackwell FFMA2) ----
__device__ __forceinline__ unsigned long long pack2(float lo, float hi) {
    unsigned long long r;
    asm("mov.b64 %0, {%1, %2};" : "=l"(r) : "f"(lo), "f"(hi));
    return r;
}
__device__ __forceinline__ void unpack2(unsigned long long v, float& lo, float& hi) {
    asm("mov.b64 {%0, %1}, %2;" : "=f"(lo), "=f"(hi) : "l"(v));
}
__device__ __forceinline__ unsigned long long ffma2(unsigned long long a,
                                                    unsigned long long b,
                                                    unsigned long long c) {
    unsigned long long d;
    asm("fma.rn.f32x2 %0, %1, %2, %3;" : "=l"(d) : "l"(a), "l"(b), "l"(c));
    return d;
}

// ---------------------------------------------------------------------------
// Kernel 1: inp_proj[b][t][j] = sum_i inp[b][t][i] * B[j][i]
// M=16384 (bt), N=4096 (j), K=64. CTA tile 128bt x 64j, 256 thr, 8bt x 4j
// per thread, accumulators paired along bt (FFMA2).
// ---------------------------------------------------------------------------
__global__ void __launch_bounds__(256) proj_kernel(const float* __restrict__ inp,
                                                   const float* __restrict__ B) {
    __shared__ __align__(16) float a_s[32][132];  // [k][bt]
    __shared__ __align__(16) float b_s[32][68];   // [k][j]

    const int tid = threadIdx.x;
    const int g0 = blockIdx.y * 128;   // bt base
    const int jb0 = blockIdx.x * 64;   // j base
    const int ty = tid >> 4;
    const int tx = tid & 15;
    const int bt0 = ty * 8;
    const int j0 = tx * 4;

    // acc2[ip][j] = (acc[2ip][j], acc[2ip+1][j]) packed over bt rows
    unsigned long long acc2[4][4];
#pragma unroll
    for (int i = 0; i < 4; i++)
#pragma unroll
        for (int j = 0; j < 4; j++) acc2[i][j] = 0ull;

#pragma unroll
    for (int kc = 0; kc < 2; kc++) {
        if (kc) __syncthreads();
#pragma unroll
        for (int it = 0; it < 4; it++) {
            int q = tid + it * 256;
            int r = q >> 3;
            int c4 = q & 7;
            float4 av = *(const float4*)(inp + (size_t)(g0 + r) * 64 + kc * 32 + c4 * 4);
            a_s[c4 * 4 + 0][r] = av.x;
            a_s[c4 * 4 + 1][r] = av.y;
            a_s[c4 * 4 + 2][r] = av.z;
            a_s[c4 * 4 + 3][r] = av.w;
        }
#pragma unroll
        for (int it = 0; it < 2; it++) {
            int q = tid + it * 256;
            int jr = q >> 3;
            int c4 = q & 7;
            float4 bv = *(const float4*)(B + (size_t)(jb0 + jr) * 64 + kc * 32 + c4 * 4);
            b_s[c4 * 4 + 0][jr] = bv.x;
            b_s[c4 * 4 + 1][jr] = bv.y;
            b_s[c4 * 4 + 2][jr] = bv.z;
            b_s[c4 * 4 + 3][jr] = bv.w;
        }
        __syncthreads();
#pragma unroll
        for (int k = 0; k < 32; k++) {
            // a pairs: 8 floats = 4 packed f32x2, loaded directly from smem
            ulonglong2 ap0 = *(const ulonglong2*)&a_s[k][bt0];
            ulonglong2 ap1 = *(const ulonglong2*)&a_s[k][bt0 + 4];
            unsigned long long ap[4] = {ap0.x, ap0.y, ap1.x, ap1.y};
            float4 bb = *(const float4*)&b_s[k][j0];
            unsigned long long bd[4] = {pack2(bb.x, bb.x), pack2(bb.y, bb.y),
                                        pack2(bb.z, bb.z), pack2(bb.w, bb.w)};
#pragma unroll
            for (int i = 0; i < 4; i++)
#pragma unroll
                for (int j = 0; j < 4; j++) acc2[i][j] = ffma2(ap[i], bd[j], acc2[i][j]);
        }
    }
    // epilogue: unpack row pairs
#pragma unroll
    for (int i = 0; i < 4; i++) {
        float r0[4], r1[4];
#pragma unroll
        for (int j = 0; j < 4; j++) unpack2(acc2[i][j], r0[j], r1[j]);
        *(float4*)(g_uproj + (size_t)(g0 + bt0 + 2 * i) * NN + jb0 + j0) =
            make_float4(r0[0], r0[1], r0[2], r0[3]);
        *(float4*)(g_uproj + (size_t)(g0 + bt0 + 2 * i + 1) * NN + jb0 + j0) =
            make_float4(r1[0], r1[1], r1[2], r1[3]);
    }
}

// ---------------------------------------------------------------------------
// Kernel 2: recurrence. One CTA per trial, 512 threads, 8 neurons/thread.
// Atomic-free rank-8 reduction: warp fold -> STS 64 half2 partials (double
// buffered) -> one barrier -> every-warp butterfly LDS reduce. u prefetched
// one full step ahead. (unchanged from R6)
// ---------------------------------------------------------------------------
__global__ void __launch_bounds__(512, 1) rnn_scan_kernel(const float* __restrict__ mg,
                                                          const float* __restrict__ ng,
                                                          float* __restrict__ xseq) {
    const int b = blockIdx.x;
    const int tid = threadIdx.x;
    const int j0 = tid * 8;
    const unsigned lane = tid & 31;
    const unsigned warp = tid >> 5;

    __shared__ __half2 part[2][4][16];

    __half2 nP[8][4], mP[8][4];
#pragma unroll
    for (int k = 0; k < 8; k++) {
        const float* nr = ng + (size_t)(j0 + k) * RR;
        const float* mr = mg + (size_t)(j0 + k) * RR;
#pragma unroll
        for (int p = 0; p < 4; p++) {
            nP[k][p] = __floats2half2_rn(nr[2 * p], nr[2 * p + 1]);
            mP[k][p] = __floats2half2_rn(mr[2 * p] * DT, mr[2 * p + 1] * DT);
        }
    }

    float x[8];
    __half2 sd[8];
    const __half2 half05 = __floats2half2_rn(0.5f, 0.5f);
#pragma unroll
    for (int k = 0; k < 8; k++) {
        x[k] = 0.f;
        sd[k] = half05;
    }

    float* xrow0 = xseq + (size_t)b * 513 * NN;
    const float4 z4 = make_float4(0.f, 0.f, 0.f, 0.f);
    *(float4*)(xrow0 + j0) = z4;
    *(float4*)(xrow0 + j0 + 4) = z4;

    const float* up = g_uproj + (size_t)b * TSTEPS * NN + j0;
    const float keep = 1.0f - DT;
    const __half2 invN2 = __floats2half2_rn(1.0f / (float)NN, 1.0f / (float)NN);
    const bool hi16 = (lane & 16) != 0;
    const bool hi8 = (lane & 8) != 0;
    const bool lo16 = !hi16;

    float4 u0 = __ldg((const float4*)up);
    float4 u1 = __ldg((const float4*)(up + 4));

    for (int t = 0; t < TSTEPS; t++) {
        float4 p0, p1;
        if (t + 1 < TSTEPS) {
            p0 = __ldg((const float4*)(up + (size_t)(t + 1) * NN));
            p1 = __ldg((const float4*)(up + (size_t)(t + 1) * NN + 4));
        } else {
            p0 = z4; p1 = z4;
        }

        __half2 h[4];
#pragma unroll
        for (int p = 0; p < 4; p++) h[p] = __floats2half2_rn(0.f, 0.f);
#pragma unroll
        for (int k = 0; k < 8; k++) {
#pragma unroll
            for (int p = 0; p < 4; p++) h[p] = __hfma2(sd[k], nP[k][p], h[p]);
        }

#pragma unroll
        for (int p = 0; p < 2; p++) {
            __half2 snd = hi16 ? h[p] : h[p + 2];
            __half2 rcv = shfl_xor_h2(snd, 16);
            h[p] = __hadd2(hi16 ? h[p + 2] : h[p], rcv);
        }
        {
            __half2 snd = hi8 ? h[0] : h[1];
            __half2 rcv = shfl_xor_h2(snd, 8);
            h[0] = __hadd2(hi8 ? h[1] : h[0], rcv);
        }
        h[0] = __hadd2(h[0], shfl_xor_h2(h[0], 4));
        h[0] = __hadd2(h[0], shfl_xor_h2(h[0], 2));
        h[0] = __hadd2(h[0], shfl_xor_h2(h[0], 1));

        const int buf = t & 1;
        if ((lane & 7) == 0) {
            part[buf][lane >> 3][warp] = h[0];
        }
        __syncthreads();

        const __half2* flat = &part[buf][0][0];
        __half2 a = flat[lane];
        __half2 c = flat[lane + 32];
#pragma unroll
        for (int d = 8; d > 0; d >>= 1) {
            a = __hadd2(a, shfl_xor_h2(a, d));
            c = __hadd2(c, shfl_xor_h2(c, d));
        }
        __half2 a2 = shfl_xor_h2(a, 16);
        __half2 c2 = shfl_xor_h2(c, 16);
        __half2 vh[4];
        vh[0] = __hmul2(lo16 ? a : a2, invN2);
        vh[1] = __hmul2(lo16 ? a2 : a, invN2);
        vh[2] = __hmul2(lo16 ? c : c2, invN2);
        vh[3] = __hmul2(lo16 ? c2 : c, invN2);

        float ua[8] = {u0.x, u0.y, u0.z, u0.w, u1.x, u1.y, u1.z, u1.w};

#pragma unroll
        for (int k = 0; k < 8; k++) {
            __half2 rh = __hmul2(vh[0], mP[k][0]);
            rh = __hfma2(vh[1], mP[k][1], rh);
            rh = __hfma2(vh[2], mP[k][2], rh);
            rh = __hfma2(vh[3], mP[k][3], rh);
            float rec = __low2float(rh) + __high2float(rh);
            x[k] = fmaf(keep, x[k], fmaf(DT, ua[k], rec));
            float s = sigmoid_fast(x[k]);
            sd[k] = __half2half2(__float2half_rn(s));
        }

        float* dst = xrow0 + (size_t)(t + 1) * NN + j0;
        *(float4*)dst = make_float4(x[0], x[1], x[2], x[3]);
        *(float4*)(dst + 4) = make_float4(x[4], x[5], x[6], x[7]);

        u0 = p0; u1 = p1;
    }
}

// ---------------------------------------------------------------------------
// Kernel 3: y[b][t][o] = sum_j sigmoid(x_seq[b][t+1][j]) * W[o][j]
// M=16384 (bt), N=64 (o), K=4096. CTA tile 128bt x 64o, 256 thr, 8bt x 4o
// per thread, accumulators paired along bt (FFMA2).
// ---------------------------------------------------------------------------
__global__ void __launch_bounds__(256) out_kernel(const float* __restrict__ xseq,
                                                  const float* __restrict__ W,
                                                  float* __restrict__ out2) {
    __shared__ __align__(16) float x_s[32][132];  // [k][bt], sigmoid applied
    __shared__ __align__(16) float w_s[32][68];   // [k][o]

    const int tid = threadIdx.x;
    const int g0 = blockIdx.x * 128;  // bt base (128 | 512: within one trial)
    const int bb = g0 >> 9;
    const int t0 = g0 & 511;
    const float* xbase = xseq + (size_t)bb * 513 * NN + (size_t)(t0 + 1) * NN;

    const int ty = tid >> 4;
    const int tx = tid & 15;
    const int bt0 = ty * 8;
    const int o0 = tx * 4;

    unsigned long long acc2[4][4];
#pragma unroll
    for (int i = 0; i < 4; i++)
#pragma unroll
        for (int j = 0; j < 4; j++) acc2[i][j] = 0ull;

    for (int kc = 0; kc < NN / 32; kc++) {
        if (kc) __syncthreads();
        // x tile: [128 bt][32 k] -> sigmoid -> x_s[k][bt]
#pragma unroll
        for (int it = 0; it < 4; it++) {
            int q = tid + it * 256;
            int r = q >> 3;
            int c4 = q & 7;
            float4 xv = *(const float4*)(xbase + (size_t)r * NN + kc * 32 + c4 * 4);
            x_s[c4 * 4 + 0][r] = sigmoid_fast(xv.x);
            x_s[c4 * 4 + 1][r] = sigmoid_fast(xv.y);
            x_s[c4 * 4 + 2][r] = sigmoid_fast(xv.z);
            x_s[c4 * 4 + 3][r] = sigmoid_fast(xv.w);
        }
        // W tile: [64 o][32 k] -> w_s[k][o]
#pragma unroll
        for (int it = 0; it < 2; it++) {
            int q = tid + it * 256;
            int o = q >> 3;
            int c4 = q & 7;
            float4 wv = *(const float4*)(W + (size_t)o * NN + kc * 32 + c4 * 4);
            w_s[c4 * 4 + 0][o] = wv.x;
            w_s[c4 * 4 + 1][o] = wv.y;
            w_s[c4 * 4 + 2][o] = wv.z;
            w_s[c4 * 4 + 3][o] = wv.w;
        }
        __syncthreads();
#pragma unroll
        for (int k = 0; k < 32; k++) {
            ulonglong2 ap0 = *(const ulonglong2*)&x_s[k][bt0];
            ulonglong2 ap1 = *(const ulonglong2*)&x_s[k][bt0 + 4];
            unsigned long long ap[4] = {ap0.x, ap0.y, ap1.x, ap1.y};
            float4 w4 = *(const float4*)&w_s[k][o0];
            unsigned long long wd[4] = {pack2(w4.x, w4.x), pack2(w4.y, w4.y),
                                        pack2(w4.z, w4.z), pack2(w4.w, w4.w)};
#pragma unroll
            for (int i = 0; i < 4; i++)
#pragma unroll
                for (int j = 0; j < 4; j++) acc2[i][j] = ffma2(ap[i], wd[j], acc2[i][j]);
        }
    }
#pragma unroll
    for (int i = 0; i < 4; i++) {
        float r0[4], r1[4];
#pragma unroll
        for (int j = 0; j < 4; j++) unpack2(acc2[i][j], r0[j], r1[j]);
        *(float4*)(out2 + (size_t)(g0 + bt0 + 2 * i) * ODIM + o0) =
            make_float4(r0[0], r0[1], r0[2], r0[3]);
        *(float4*)(out2 + (size_t)(g0 + bt0 + 2 * i + 1) * ODIM + o0) =
            make_float4(r1[0], r1[1], r1[2], r1[3]);
    }
}

// ---------------------------------------------------------------------------
extern "C" void kernel_launch(void* const* d_in, const int* in_sizes, int n_in,
                              void* d_out, int out_size) {
    const float* inp = (const float*)d_in[0];  // [32,512,64]
    const float* B = (const float*)d_in[1];    // [4096,64]
    const float* W = (const float*)d_in[2];    // [64,4096]
    const float* m = (const float*)d_in[3];    // [4096,8]
    const float* n = (const float*)d_in[4];    // [4096,8]

    float* xseq = (float*)d_out;               // [32,513,4096]
    float* out2 = (float*)d_out + XSEQ_ELEMS;  // [32,512,64]

    {
        dim3 grid(NN / 64, (NTRI * TSTEPS) / 128);
        proj_kernel<<<grid, 256>>>(inp, B);
    }
    rnn_scan_kernel<<<NTRI, 512>>>(m, n, xseq);
    out_kernel<<<(NTRI * TSTEPS) / 128, 256>>>(xseq, W, out2);
}